// round 17
// baseline (speedup 1.0000x reference)
#include <cuda_runtime.h>
#include <cuda_bf16.h>
#include <stdint.h>

// ===================== problem constants =====================
#define D_IN 256
#define D_G  512
#define VBS  128

// ===================== SMEM layout (bytes) ===================
#define OFF_PSUM  0               // f32[512] -> scale
#define OFF_PSQ   2048            // f32[512] -> shift
#define OFF_A     4096            // 2 slots x 10240 (64 rows x 80B pitch, hi+lo)
#define A_SLOT    10240
#define A_LO      5120
#define OFF_B     24576           // 3 slots x 16384 (B-hi only), fragment order
#define B_SLOT    16384
#define OFF_CBUF  73728           // f32[64][520] = 133120 -> end 206848
#define DYN_SMEM  206848
#define CPITCH    520

// ===================== W fragment scratch (kt-major) =========
// uint2 index = (kt*64 + nt_glob)*32 + lane   (kt 0..15, nt_glob 0..63)
//   n  = nt_glob*8 + (lane>>2)
//   k0 = kt*16 + (lane&3)*2
//   .x = pack(W[n][k0],   W[n][k0+1])
//   .y = pack(W[n][k0+8], W[n][k0+9])
__device__ uint2 g_Bhi2[16 * 64 * 32];
__device__ uint2 g_Blo2[16 * 64 * 32];

static __device__ __forceinline__ uint32_t packbf(float a, float b) {
    union { __nv_bfloat16 h[2]; uint32_t u; } U;
    U.h[0] = __float2bfloat16(a);
    U.h[1] = __float2bfloat16(b);
    return U.u;
}

__global__ void prep_w_kernel(const float* __restrict__ W) {
    int idx  = blockIdx.x * 256 + threadIdx.x;   // 0..32767
    int lane = idx & 31;
    int nt   = (idx >> 5) & 63;
    int kt   = idx >> 11;
    int n  = nt * 8 + (lane >> 2);
    int k0 = kt * 16 + (lane & 3) * 2;
    float w00 = W[n * D_IN + k0],     w01 = W[n * D_IN + k0 + 1];
    float w10 = W[n * D_IN + k0 + 8], w11 = W[n * D_IN + k0 + 9];
    __nv_bfloat16 h00 = __float2bfloat16(w00), h01 = __float2bfloat16(w01);
    __nv_bfloat16 h10 = __float2bfloat16(w10), h11 = __float2bfloat16(w11);
    uint2 hi, lo;
    { union { __nv_bfloat16 h[2]; uint32_t u; } U;
      U.h[0] = h00; U.h[1] = h01; hi.x = U.u;
      U.h[0] = h10; U.h[1] = h11; hi.y = U.u; }
    lo.x = packbf(w00 - __bfloat162float(h00), w01 - __bfloat162float(h01));
    lo.y = packbf(w10 - __bfloat162float(h10), w11 - __bfloat162float(h11));
    g_Bhi2[idx] = hi;
    g_Blo2[idx] = lo;
}

// ===================== device helpers ========================
static __device__ __forceinline__ uint32_t smem_u32(const void* p) {
    uint32_t a;
    asm("{ .reg .u64 t; cvta.to.shared.u64 t, %1; cvt.u32.u64 %0, t; }"
        : "=r"(a) : "l"(p));
    return a;
}

#define CP_ASYNC16(dst, src) \
    asm volatile("cp.async.cg.shared.global [%0], [%1], 16;" \
                 :: "r"(dst), "l"(src) : "memory")
#define CP_COMMIT() asm volatile("cp.async.commit_group;" ::: "memory")
#define CP_WAIT1()  asm volatile("cp.async.wait_group 1;" ::: "memory")

static __device__ __forceinline__ void mma16816(float d[4],
                                                uint32_t a0, uint32_t a1,
                                                uint32_t a2, uint32_t a3,
                                                uint32_t b0, uint32_t b1) {
    asm volatile(
        "mma.sync.aligned.m16n8k16.row.col.f32.bf16.bf16.f32 "
        "{%0,%1,%2,%3}, {%4,%5,%6,%7}, {%8,%9}, {%0,%1,%2,%3};"
        : "+f"(d[0]), "+f"(d[1]), "+f"(d[2]), "+f"(d[3])
        : "r"(a0), "r"(a1), "r"(a2), "r"(a3), "r"(b0), "r"(b1));
}

static __device__ __forceinline__ void ldmx4(uint32_t r[4], uint32_t addr) {
    asm volatile("ldmatrix.sync.aligned.m8n8.x4.shared.b16 {%0,%1,%2,%3}, [%4];"
                 : "=r"(r[0]), "=r"(r[1]), "=r"(r[2]), "=r"(r[3]) : "r"(addr));
}

// stage A chunk kc (64 rows x 32 K) into A slot, hi/lo bf16, pitch 80 B
static __device__ __forceinline__ void stageA(
    const float* __restrict__ feat, int grow0, char* smem, int tid, int kc, int slot)
{
    int r  = tid >> 3;          // 0..63
    int c4 = (tid & 7) * 4;     // 0..28
    float4 f = *(const float4*)(feat + (size_t)(grow0 + r) * D_IN + kc * 32 + c4);
    uint2 hi, lo;
    hi.x = packbf(f.x, f.y);  hi.y = packbf(f.z, f.w);
    __nv_bfloat16 hx = __float2bfloat16(f.x), hy = __float2bfloat16(f.y);
    __nv_bfloat16 hz = __float2bfloat16(f.z), hw = __float2bfloat16(f.w);
    lo.x = packbf(f.x - __bfloat162float(hx), f.y - __bfloat162float(hy));
    lo.y = packbf(f.z - __bfloat162float(hz), f.w - __bfloat162float(hw));
    char* base = smem + OFF_A + slot * A_SLOT + r * 80 + c4 * 2;
    *(uint2*)(base)        = hi;
    *(uint2*)(base + A_LO) = lo;
}

// issue cp.async for B-hi(kt) into slot: 16 KB, 2x16B per thread
static __device__ __forceinline__ void issueBh(uint32_t sb, int tid, int kt, int slot) {
    const char* sh = (const char*)g_Bhi2 + (size_t)kt * 16384;
    uint32_t dh = sb + OFF_B + slot * B_SLOT + tid * 32;
    CP_ASYNC16(dh,      sh + tid * 32);
    CP_ASYNC16(dh + 16, sh + tid * 32 + 16);
    CP_COMMIT();
}

// GEMM for one 64-row half; acc[mt][nt][4]: warp tile rows rg*32.., cols cg*64..
static __device__ __forceinline__ void gemm_half(
    const float* __restrict__ feat, int grow0, char* smem, uint32_t sb,
    int tid, int w, int lane, float acc[2][8][4])
{
    const int rg = w >> 3, cg = w & 7;
    const uint32_t a_frag = (uint32_t)((rg * 32 + (lane & 15)) * 80 + (lane >> 4) * 16);
    const uint32_t b_frag = (uint32_t)(((cg * 8) * 32 + lane) * 8);

    stageA(feat, grow0, smem, tid, 0, 0);
    issueBh(sb, tid, 0, 0);   // group kt=0
    issueBh(sb, tid, 1, 1);   // group kt=1

    int slot = 0;             // slot of current kt (mod 3)
    #pragma unroll 1
    for (int kt = 0; kt < 16; kt++) {
        CP_WAIT1();           // all groups except the newest (kt+1) complete
        __syncthreads();      // copies visible to all; prev-slot reads done

        // keep one cp.async group per iteration (numbering invariant)
        int ns = slot + 2; if (ns >= 3) ns -= 3;
        if (kt + 2 < 16) issueBh(sb, tid, kt + 2, ns);
        else             CP_COMMIT();
        if ((kt & 1) == 0 && kt + 2 < 16)
            stageA(feat, grow0, smem, tid, (kt >> 1) + 1, ((kt >> 1) + 1) & 1);

        // ---- B-lo: direct global loads, consumed ~2 passes later ----
        const uint2* blp = g_Blo2 + ((size_t)kt * 64 + cg * 8) * 32 + lane;
        uint2 bl[8];
        #pragma unroll
        for (int nt = 0; nt < 8; nt++) bl[nt] = __ldg(blp + nt * 32);

        const uint32_t aslot = sb + OFF_A + (((uint32_t)kt >> 1) & 1) * A_SLOT;
        const char*    bslot = smem + OFF_B + slot * B_SLOT;
        uint32_t ah0 = aslot + a_frag + (kt & 1) * 32;
        uint32_t al0 = ah0 + A_LO;

        uint2 bh[8];
        #pragma unroll
        for (int nt = 0; nt < 8; nt++)
            bh[nt] = *(const uint2*)(bslot + b_frag + nt * 256);

        uint32_t ah[2][4];
        ldmx4(ah[0], ah0);
        ldmx4(ah[1], ah0 + 16 * 80);

        // ---- pass 1: Ah * Bh ----
        #pragma unroll
        for (int nt = 0; nt < 8; nt++) {
            mma16816(acc[0][nt], ah[0][0], ah[0][1], ah[0][2], ah[0][3], bh[nt].x, bh[nt].y);
            mma16816(acc[1][nt], ah[1][0], ah[1][1], ah[1][2], ah[1][3], bh[nt].x, bh[nt].y);
        }
        // ---- pass 2: Al * Bh ----
        {
            uint32_t al[2][4];
            ldmx4(al[0], al0);
            ldmx4(al[1], al0 + 16 * 80);
            #pragma unroll
            for (int nt = 0; nt < 8; nt++) {
                mma16816(acc[0][nt], al[0][0], al[0][1], al[0][2], al[0][3], bh[nt].x, bh[nt].y);
                mma16816(acc[1][nt], al[1][0], al[1][1], al[1][2], al[1][3], bh[nt].x, bh[nt].y);
            }
        }
        // ---- pass 3: Ah * Bl (bl arrived from L2 during passes 1-2) ----
        #pragma unroll
        for (int nt = 0; nt < 8; nt++) {
            mma16816(acc[0][nt], ah[0][0], ah[0][1], ah[0][2], ah[0][3], bl[nt].x, bl[nt].y);
            mma16816(acc[1][nt], ah[1][0], ah[1][1], ah[1][2], ah[1][3], bl[nt].x, bl[nt].y);
        }

        if (++slot == 3) slot = 0;
    }
}

// Column partial sums/sumsq via smem atomicAdd (degree-2 contention).
static __device__ __forceinline__ void reduce_stats(
    float acc[2][8][4], float* psum, float* psq, int w, int lane)
{
    const int cg = w & 7;
    #pragma unroll
    for (int nt = 0; nt < 8; nt++) {
        float s0 = acc[0][nt][0] + acc[0][nt][2] + acc[1][nt][0] + acc[1][nt][2];
        float s1 = acc[0][nt][1] + acc[0][nt][3] + acc[1][nt][1] + acc[1][nt][3];
        float q0 = acc[0][nt][0] * acc[0][nt][0] + acc[0][nt][2] * acc[0][nt][2]
                 + acc[1][nt][0] * acc[1][nt][0] + acc[1][nt][2] * acc[1][nt][2];
        float q1 = acc[0][nt][1] * acc[0][nt][1] + acc[0][nt][3] * acc[0][nt][3]
                 + acc[1][nt][1] * acc[1][nt][1] + acc[1][nt][3] * acc[1][nt][3];
        #pragma unroll
        for (int d = 4; d < 32; d <<= 1) {
            s0 += __shfl_xor_sync(0xFFFFFFFFu, s0, d);
            s1 += __shfl_xor_sync(0xFFFFFFFFu, s1, d);
            q0 += __shfl_xor_sync(0xFFFFFFFFu, q0, d);
            q1 += __shfl_xor_sync(0xFFFFFFFFu, q1, d);
        }
        if (lane < 4) {
            int c0 = cg * 64 + nt * 8 + 2 * lane;
            atomicAdd(&psum[c0],     s0);
            atomicAdd(&psum[c0 + 1], s1);
            atomicAdd(&psq[c0],      q0);
            atomicAdd(&psq[c0 + 1],  q1);
        }
    }
}

// Warp-per-4-rows sparsemax, vectorized mapping c = lane*16 + t.
template <bool PRE_NORMALIZED>
static __device__ __forceinline__ void sparsemax_rows(
    const float* __restrict__ cb, const float* __restrict__ scale,
    const float* __restrict__ shift, const float* __restrict__ priors,
    float* __restrict__ out, int grow_base, int w, int lane)
{
    #pragma unroll 1
    for (int q = 0; q < 4; q++) {
        const int lr = w * 4 + q;
        const int grow = grow_base + lr;
        const int c0 = lane * 16;
        const float* prow = priors + (size_t)grow * D_G + c0;
        const float* crow = cb + lr * CPITCH + c0;
        float v[16];
        float vmax = -3.4e38f;
        #pragma unroll
        for (int j = 0; j < 4; j++) {
            float4 p = *(const float4*)(prow + 4 * j);
            float4 z = *(const float4*)(crow + 4 * j);
            if (!PRE_NORMALIZED) {
                float4 sc = *(const float4*)(scale + c0 + 4 * j);
                float4 sh = *(const float4*)(shift + c0 + 4 * j);
                z.x = fmaf(z.x, sc.x, sh.x);
                z.y = fmaf(z.y, sc.y, sh.y);
                z.z = fmaf(z.z, sc.z, sh.z);
                z.w = fmaf(z.w, sc.w, sh.w);
            }
            v[4*j+0] = z.x * p.x; v[4*j+1] = z.y * p.y;
            v[4*j+2] = z.z * p.z; v[4*j+3] = z.w * p.w;
            vmax = fmaxf(vmax, fmaxf(fmaxf(v[4*j], v[4*j+1]), fmaxf(v[4*j+2], v[4*j+3])));
        }
        #pragma unroll
        for (int d = 16; d > 0; d >>= 1)
            vmax = fmaxf(vmax, __shfl_xor_sync(0xFFFFFFFFu, vmax, d));

        // Newton on g(tau) = sum(relu(v - tau)) - 1 : convex, piecewise linear
        float tau = vmax - 1.0f;
        #pragma unroll 1
        for (int it = 0; it < 32; it++) {
            float s = 0.f, k = 0.f;
            #pragma unroll
            for (int t = 0; t < 16; t++)
                if (v[t] > tau) { s += v[t]; k += 1.0f; }
            #pragma unroll
            for (int d = 16; d > 0; d >>= 1) {
                s += __shfl_xor_sync(0xFFFFFFFFu, s, d);
                k += __shfl_xor_sync(0xFFFFFFFFu, k, d);
            }
            if (k < 0.5f) break;
            float tn = (s - 1.0f) / k;
            if (tn == tau) break;
            tau = tn;
        }
        float* orow = out + (size_t)grow * D_G + c0;
        #pragma unroll
        for (int j = 0; j < 4; j++) {
            float4 r;
            r.x = fmaxf(v[4*j+0] - tau, 0.0f);
            r.y = fmaxf(v[4*j+1] - tau, 0.0f);
            r.z = fmaxf(v[4*j+2] - tau, 0.0f);
            r.w = fmaxf(v[4*j+3] - tau, 0.0f);
            *(float4*)(orow + 4 * j) = r;
        }
    }
}

// ===================== fused kernel ==========================
__global__ void __launch_bounds__(512, 1)
attentive_fused_kernel(const float* __restrict__ priors,
                       const float* __restrict__ feat,
                       const float* __restrict__ gamma,
                       const float* __restrict__ beta,
                       float* __restrict__ out)
{
    extern __shared__ char smem[];
    const uint32_t sb = smem_u32(smem);
    const int tid = threadIdx.x;
    const int w = tid >> 5, lane = tid & 31;
    const int row0 = blockIdx.x * VBS;

    float* psum = (float*)(smem + OFF_PSUM);
    float* psq  = (float*)(smem + OFF_PSQ);
    float* cb   = (float*)(smem + OFF_CBUF);

    psum[tid] = 0.f;
    psq[tid]  = 0.f;
    __syncthreads();

    float acc[2][8][4];

    // ---------- half 0: rows row0 .. row0+63 ----------
    #pragma unroll
    for (int mt = 0; mt < 2; mt++)
        #pragma unroll
        for (int nt = 0; nt < 8; nt++)
            #pragma unroll
            for (int e = 0; e < 4; e++) acc[mt][nt][e] = 0.f;
    gemm_half(feat, row0, smem, sb, tid, w, lane, acc);
    reduce_stats(acc, psum, psq, w, lane);

    // spill raw C (rows 0-63) to SMEM row-major
    {
        const int rg = w >> 3, cg = w & 7;
        #pragma unroll
        for (int mt = 0; mt < 2; mt++) {
            int row = rg * 32 + mt * 16 + (lane >> 2);
            #pragma unroll
            for (int nt = 0; nt < 8; nt++) {
                int c = cg * 64 + nt * 8 + 2 * (lane & 3);
                *(float2*)(cb + row * CPITCH + c) =
                    make_float2(acc[mt][nt][0], acc[mt][nt][1]);
                *(float2*)(cb + (row + 8) * CPITCH + c) =
                    make_float2(acc[mt][nt][2], acc[mt][nt][3]);
            }
        }
    }

    // ---------- half 1: rows row0+64 .. row0+127 ----------
    #pragma unroll
    for (int mt = 0; mt < 2; mt++)
        #pragma unroll
        for (int nt = 0; nt < 8; nt++)
            #pragma unroll
            for (int e = 0; e < 4; e++) acc[mt][nt][e] = 0.f;
    gemm_half(feat, row0 + 64, smem, sb, tid, w, lane, acc);
    reduce_stats(acc, psum, psq, w, lane);
    __syncthreads();

    // ---------- finalize GBN: scale->psum, shift->psq (in place) ----------
    {
        int c = tid;
        float m  = psum[c] * (1.0f / 128.0f);
        float ms = psq[c]  * (1.0f / 128.0f);
        float var = ms - m * m;
        float sc = gamma[c] * rsqrtf(var + 1e-5f);
        psum[c] = sc;                  // scale
        psq[c]  = beta[c] - m * sc;    // shift
    }
    __syncthreads();

    // ---------- sparsemax rows 0-63 (normalize on the fly) ----------
    sparsemax_rows<false>(cb, psum, psq, priors, out, row0, w, lane);
    __syncthreads();

    // ---------- write normalized half-1 regs into SMEM ----------
    {
        const int rg = w >> 3, cg = w & 7;
        #pragma unroll
        for (int mt = 0; mt < 2; mt++) {
            int row = rg * 32 + mt * 16 + (lane >> 2);
            #pragma unroll
            for (int nt = 0; nt < 8; nt++) {
                int c = cg * 64 + nt * 8 + 2 * (lane & 3);
                float z0 = fmaf(acc[mt][nt][0], psum[c],     psq[c]);
                float z1 = fmaf(acc[mt][nt][1], psum[c + 1], psq[c + 1]);
                float z2 = fmaf(acc[mt][nt][2], psum[c],     psq[c]);
                float z3 = fmaf(acc[mt][nt][3], psum[c + 1], psq[c + 1]);
                *(float2*)(cb + row * CPITCH + c)       = make_float2(z0, z1);
                *(float2*)(cb + (row + 8) * CPITCH + c) = make_float2(z2, z3);
            }
        }
    }
    __syncthreads();

    // ---------- sparsemax rows 64-127 ----------
    sparsemax_rows<true>(cb, psum, psq, priors, out, row0 + 64, w, lane);
}

// ===================== launch ================================
extern "C" void kernel_launch(void* const* d_in, const int* in_sizes, int n_in,
                              void* d_out, int out_size) {
    (void)in_sizes; (void)n_in; (void)out_size;
    const float* priors = (const float*)d_in[0];   // [65536, 512]
    const float* feat   = (const float*)d_in[1];   // [65536, 256]
    const float* W      = (const float*)d_in[2];   // [512, 256]
    const float* gamma  = (const float*)d_in[3];   // [512]
    const float* beta   = (const float*)d_in[4];   // [512]
    float* out = (float*)d_out;                    // [65536, 512]

    cudaFuncSetAttribute(attentive_fused_kernel,
                         cudaFuncAttributeMaxDynamicSharedMemorySize, DYN_SMEM);

    prep_w_kernel<<<128, 256>>>(W);
    attentive_fused_kernel<<<512, 512, DYN_SMEM>>>(priors, feat, gamma, beta, out);
}